// round 4
// baseline (speedup 1.0000x reference)
#include <cuda_runtime.h>
#include <cuda_bf16.h>
#include <math.h>

// GLIF recurrence, T=4, single fused kernel.
// Warp 0 lanes 0-7 compute the per-channel sigmoids in parallel, derive the
// 9 constants into shared memory; all threads then run the streaming
// 4-step recurrence on one float4 each.
//
// x: (B=16, PLANE=2048, L=1024) fp32. out: final spike map, fp32 {0,1}.

#define GLIF_T     4
#define GLIF_PLANE 2048
#define GLIF_L     1024

// shared param slots:
// 0: A = 1 - al*(1 - sigmoid(tau))
// 1: omg = 1 - ga
// 2: negLk = -(1-al)*sigmoid(leak)
// 3: negR  = -(1-ga)*sigmoid(reVth)
// 4: vth   = sigmoid(Vth)
// 5..8: s_t = 1 - be*(1 - sigmoid(conduct[t,c]))

__global__ void __launch_bounds__(256, 8) glif_fused_kernel(
    const float* __restrict__ x,
    const float* __restrict__ alpha,
    const float* __restrict__ beta,
    const float* __restrict__ gamma,
    const float* __restrict__ tau,
    const float* __restrict__ Vth,
    const float* __restrict__ leak,
    const float* __restrict__ reVth,
    const float* __restrict__ conduct,
    float* __restrict__ out)
{
    __shared__ float sp[9];

    const int row = blockIdx.x;                 // row = b*PLANE + c
    const int c   = row & (GLIF_PLANE - 1);
    const size_t base = (size_t)row * GLIF_L;

    // Issue the x load BEFORE the barrier — independent of params, so the
    // DRAM latency overlaps the param computation below.
    const float4 xv =
        __ldcs(reinterpret_cast<const float4*>(x + base) + threadIdx.x);

    if (threadIdx.x < 32) {
        const int lane = threadIdx.x;

        // Gates: arch_act(sigmoid(p)) == (p > 0). Broadcast loads, all lanes.
        const float al = (__ldg(&alpha[c]) > 0.0f) ? 1.0f : 0.0f;
        const float be = (__ldg(&beta[c])  > 0.0f) ? 1.0f : 0.0f;
        const float ga = (__ldg(&gamma[c]) > 0.0f) ? 1.0f : 0.0f;

        // Lanes 0-7 each own one sigmoid.
        float v = 0.0f;
        if      (lane == 0) v = tau[c];
        else if (lane == 1) v = Vth[c];
        else if (lane == 2) v = leak[c];
        else if (lane == 3) v = reVth[c];
        else if (lane >= 4 && lane < 8) v = conduct[(lane - 4) * GLIF_PLANE + c];

        const float sig = 1.0f / (1.0f + expf(-v));

        if (lane == 0) {
            sp[0] = 1.0f - al * (1.0f - sig);   // A
            sp[1] = 1.0f - ga;                  // omg
        } else if (lane == 1) {
            sp[4] = sig;                        // vth
        } else if (lane == 2) {
            sp[2] = -((1.0f - al) * sig);       // negLk
        } else if (lane == 3) {
            sp[3] = -((1.0f - ga) * sig);       // negR
        } else if (lane >= 4 && lane < 8) {
            sp[5 + (lane - 4)] = 1.0f - be * (1.0f - sig);  // s_t
        }
    }
    __syncthreads();

    const float A     = sp[0];
    const float omg   = sp[1];
    const float negLk = sp[2];
    const float negR  = sp[3];
    const float vth   = sp[4];
    const float s0    = sp[5];
    const float sv0   = sp[6];
    const float sv1   = sp[7];
    const float sv2   = sp[8];

    float xl[4] = {xv.x, xv.y, xv.z, xv.w};
    float sv[3] = {sv0, sv1, sv2};
    float ov[4];

#pragma unroll
    for (int j = 0; j < 4; ++j) {
        const float xj = xl[j];
        // t = 0: u=0, o=0  ->  u1 = x*s0 - Lk
        float u = fmaf(xj, s0, negLk);
        bool  o = (u > vth);
#pragma unroll
        for (int t = 0; t < 3; ++t) {
            // reference order: ((A*u)*(1-ga*o) - Lk) + x*s - R*o
            const float g = o ? omg : 1.0f;
            float m = (A * u) * g;
            m = m + negLk;
            m = fmaf(xj, sv[t], m);
            if (o) m = m + negR;
            o = (m > vth);
            u = m;
        }
        ov[j] = o ? 1.0f : 0.0f;
    }

    float4 res;
    res.x = ov[0]; res.y = ov[1]; res.z = ov[2]; res.w = ov[3];
    __stcs(reinterpret_cast<float4*>(out + base) + threadIdx.x, res);
}

extern "C" void kernel_launch(void* const* d_in, const int* in_sizes, int n_in,
                              void* d_out, int out_size) {
    const float* x       = (const float*)d_in[0];
    const float* alpha   = (const float*)d_in[1];
    const float* beta    = (const float*)d_in[2];
    const float* gamma   = (const float*)d_in[3];
    const float* tau     = (const float*)d_in[4];
    const float* Vth     = (const float*)d_in[5];
    const float* leak    = (const float*)d_in[6];
    const float* reVth   = (const float*)d_in[7];
    const float* conduct = (const float*)d_in[8];
    float* out = (float*)d_out;

    const int rows = out_size / GLIF_L;   // B * PLANE = 32768
    glif_fused_kernel<<<rows, 256>>>(x, alpha, beta, gamma, tau, Vth, leak,
                                     reVth, conduct, out);
}

// round 5
// speedup vs baseline: 1.6934x; 1.6934x over previous
#include <cuda_runtime.h>
#include <cuda_bf16.h>
#include <math.h>

// GLIF recurrence, T=4, single fused kernel, ONE BLOCK PER CHANNEL.
// Block = 256 threads handles all 16 batches of its channel (16 float4/thread),
// so the per-channel param computation (warp-parallel sigmoids + one barrier)
// is amortized over 128 KiB of traffic instead of 8 KiB.
//
// x: (B=16, PLANE=2048, L=1024) fp32. out: final spike map, fp32 {0,1}.

#define GLIF_T     4
#define GLIF_PLANE 2048
#define GLIF_L     1024
#define GLIF_B     16

__global__ void __launch_bounds__(256) glif_channel_kernel(
    const float* __restrict__ x,
    const float* __restrict__ alpha,
    const float* __restrict__ beta,
    const float* __restrict__ gamma,
    const float* __restrict__ tau,
    const float* __restrict__ Vth,
    const float* __restrict__ leak,
    const float* __restrict__ reVth,
    const float* __restrict__ conduct,
    float* __restrict__ out)
{
    __shared__ float sp[9];

    const int c   = blockIdx.x;            // channel
    const int tid = threadIdx.x;

    const size_t row4  = (size_t)GLIF_PLANE * (GLIF_L / 4);  // float4 stride per batch
    const size_t base4 = (size_t)c * (GLIF_L / 4) + tid;
    const float4* xp = reinterpret_cast<const float4*>(x) + base4;
    float4*       op = reinterpret_cast<float4*>(out) + base4;

    // ---- prefetch chunk 0 (independent of params) ----
    float4 xv[4];
#pragma unroll
    for (int u = 0; u < 4; ++u)
        xv[u] = __ldcs(xp + (size_t)u * row4);

    // ---- per-channel params: warp 0, lanes 0-7 each own one sigmoid ----
    if (tid < 32) {
        const int lane = tid;
        const float al = (__ldg(&alpha[c]) > 0.0f) ? 1.0f : 0.0f;  // arch_act(sigmoid) == (p>0)
        const float be = (__ldg(&beta[c])  > 0.0f) ? 1.0f : 0.0f;
        const float ga = (__ldg(&gamma[c]) > 0.0f) ? 1.0f : 0.0f;

        float v = 0.0f;
        if      (lane == 0) v = tau[c];
        else if (lane == 1) v = Vth[c];
        else if (lane == 2) v = leak[c];
        else if (lane == 3) v = reVth[c];
        else if (lane >= 4 && lane < 8) v = conduct[(lane - 4) * GLIF_PLANE + c];

        const float sig = 1.0f / (1.0f + expf(-v));

        if (lane == 0) {
            sp[0] = 1.0f - al * (1.0f - sig);   // A
            sp[1] = 1.0f - ga;                  // omg
        } else if (lane == 1) {
            sp[4] = sig;                        // vth
        } else if (lane == 2) {
            sp[2] = -((1.0f - al) * sig);       // negLk
        } else if (lane == 3) {
            sp[3] = -((1.0f - ga) * sig);       // negR
        } else if (lane >= 4 && lane < 8) {
            sp[5 + (lane - 4)] = 1.0f - be * (1.0f - sig);  // s_t
        }
    }
    __syncthreads();

    const float A     = sp[0];
    const float omg   = sp[1];
    const float negLk = sp[2];
    const float negR  = sp[3];
    const float vth   = sp[4];
    const float s0    = sp[5];
    const float sv[3] = {sp[6], sp[7], sp[8]};

    // ---- stream 16 batches, double-buffered in chunks of 4 ----
#pragma unroll
    for (int chunk = 0; chunk < 4; ++chunk) {
        float4 nv[4];
        if (chunk < 3) {
#pragma unroll
            for (int u = 0; u < 4; ++u)
                nv[u] = __ldcs(xp + (size_t)((chunk + 1) * 4 + u) * row4);
        }

#pragma unroll
        for (int u = 0; u < 4; ++u) {
            float xl[4] = {xv[u].x, xv[u].y, xv[u].z, xv[u].w};
            float ov[4];
#pragma unroll
            for (int j = 0; j < 4; ++j) {
                const float xj = xl[j];
                // t=0: u=0, o=0 -> u1 = x*s0 - Lk
                float uu = fmaf(xj, s0, negLk);
                bool  o  = (uu > vth);
#pragma unroll
                for (int t = 0; t < 3; ++t) {
                    // reference order: ((A*u)*(1-ga*o) - Lk) + x*s - R*o
                    const float g = o ? omg : 1.0f;
                    float m = (A * uu) * g;
                    m = m + negLk;
                    m = fmaf(xj, sv[t], m);
                    if (o) m = m + negR;
                    o = (m > vth);
                    uu = m;
                }
                ov[j] = o ? 1.0f : 0.0f;
            }
            float4 res;
            res.x = ov[0]; res.y = ov[1]; res.z = ov[2]; res.w = ov[3];
            __stcs(op + (size_t)(chunk * 4 + u) * row4, res);
        }

#pragma unroll
        for (int u = 0; u < 4; ++u) xv[u] = nv[u];
    }
}

extern "C" void kernel_launch(void* const* d_in, const int* in_sizes, int n_in,
                              void* d_out, int out_size) {
    const float* x       = (const float*)d_in[0];
    const float* alpha   = (const float*)d_in[1];
    const float* beta    = (const float*)d_in[2];
    const float* gamma   = (const float*)d_in[3];
    const float* tau     = (const float*)d_in[4];
    const float* Vth     = (const float*)d_in[5];
    const float* leak    = (const float*)d_in[6];
    const float* reVth   = (const float*)d_in[7];
    const float* conduct = (const float*)d_in[8];
    float* out = (float*)d_out;

    glif_channel_kernel<<<GLIF_PLANE, 256>>>(x, alpha, beta, gamma, tau, Vth,
                                             leak, reVth, conduct, out);
}